// round 12
// baseline (speedup 1.0000x reference)
#include <cuda_runtime.h>
#include <cuda_bf16.h>
#include <math.h>
#include <stdint.h>

#define RR 36
#define WW 50
#define DD 256
#define NI 128
#define NJ 128

// ---------------- split bf16 global scratch (allocation-free) --------------
__device__ __align__(16) __nv_bfloat16 g_Ahi[NI * RR * DD];
__device__ __align__(16) __nv_bfloat16 g_Alo[NI * RR * DD];
__device__ __align__(16) __nv_bfloat16 g_Bhi[NJ * WW * DD];
__device__ __align__(16) __nv_bfloat16 g_Blo[NJ * WW * DD];

// ---------------- SMEM layout (bytes) --------------------------------------
// K-chunk = 32 cols bf16 = 64B data + 16B pad -> 80B row stride.
// Stage = 4 tiles (Ahi,Alo,Bhi,Blo) x 128 rows x 80B = 40960B; 2 stages.
#define RS       80
#define TILE_B   (128 * RS)          /* 10240 */
#define STAGE_B  (4 * TILE_B)        /* 40960 */
#define SMEM_TOTAL (2 * STAGE_B)     /* 81920 */
#define T_AHI 0
#define T_ALO TILE_B
#define T_BHI (2 * TILE_B)
#define T_BLO (3 * TILE_B)
// Sinkhorn region aliases the stages (used only after GEMM completes)
#define WPAD    53
#define PAIR_F  (RR * WPAD)          /* 1908 floats */
#define SM_P_F  (4 * PAIR_F)         /* 7632 floats; S+P = 61056B < 81920B */

// ---------------- PTX helpers (base-target instructions only) ---------------
__device__ __forceinline__ uint32_t smem_u32(const void* p) {
    uint32_t a;
    asm("{ .reg .u64 t; cvta.to.shared.u64 t, %1; cvt.u32.u64 %0, t; }"
        : "=r"(a) : "l"(p));
    return a;
}
__device__ __forceinline__ void cp16(uint32_t s, const void* g) {
    asm volatile("cp.async.ca.shared.global [%0], [%1], 16;" :: "r"(s), "l"(g));
}
#define CP_COMMIT() asm volatile("cp.async.commit_group;" ::: "memory")
#define CP_WAIT(n)  asm volatile("cp.async.wait_group %0;" :: "n"(n) : "memory")

#define LDSM_X4(r, addr)                                                      \
    asm volatile("ldmatrix.sync.aligned.m8n8.x4.shared.b16 {%0,%1,%2,%3}, [%4];" \
                 : "=r"((r)[0]), "=r"((r)[1]), "=r"((r)[2]), "=r"((r)[3])     \
                 : "r"(addr))

#define MMA16816(d, a, b0, b1)                                                \
    asm volatile("mma.sync.aligned.m16n8k16.row.col.f32.bf16.bf16.f32 "       \
                 "{%0,%1,%2,%3}, {%4,%5,%6,%7}, {%8,%9}, {%0,%1,%2,%3};"      \
                 : "+f"((d)[0]), "+f"((d)[1]), "+f"((d)[2]), "+f"((d)[3])     \
                 : "r"((a)[0]), "r"((a)[1]), "r"((a)[2]), "r"((a)[3]),        \
                   "r"(b0), "r"(b1))

// ---------------------------------------------------------------------------
// Prep: L2-normalize each 256-d row, emit split bf16 (hi, lo). 1 warp/row.
// ---------------------------------------------------------------------------
__global__ __launch_bounds__(256)
void prep_kernel(const float* __restrict__ imgs, const float* __restrict__ caps) {
    int gw   = blockIdx.x * 8 + (threadIdx.x >> 5);
    int lane = threadIdx.x & 31;
    const int na = NI * RR;
    const float* src;
    __nv_bfloat16 *dhi, *dlo;
    if (gw < na) {
        src = imgs + (size_t)gw * DD;
        dhi = g_Ahi + (size_t)gw * DD;
        dlo = g_Alo + (size_t)gw * DD;
    } else {
        int g2 = gw - na;
        if (g2 >= NJ * WW) return;
        src = caps + (size_t)g2 * DD;
        dhi = g_Bhi + (size_t)g2 * DD;
        dlo = g_Blo + (size_t)g2 * DD;
    }
    float4 x0 = ((const float4*)src)[lane];
    float4 x1 = ((const float4*)src)[lane + 32];
    float ss = x0.x*x0.x + x0.y*x0.y + x0.z*x0.z + x0.w*x0.w
             + x1.x*x1.x + x1.y*x1.y + x1.z*x1.z + x1.w*x1.w;
#pragma unroll
    for (int o = 16; o; o >>= 1) ss += __shfl_xor_sync(0xffffffffu, ss, o);
    float sc = 1.0f / fmaxf(sqrtf(ss), 1e-8f);
    float xs[8] = { x0.x*sc, x0.y*sc, x0.z*sc, x0.w*sc,
                    x1.x*sc, x1.y*sc, x1.z*sc, x1.w*sc };
#pragma unroll
    for (int h = 0; h < 2; h++) {
        int b = h * 128 + 4 * lane;
#pragma unroll
        for (int q = 0; q < 2; q++) {
            float a = xs[h*4 + q*2], c = xs[h*4 + q*2 + 1];
            __nv_bfloat16 ah = __float2bfloat16(a);
            __nv_bfloat16 ch = __float2bfloat16(c);
            __nv_bfloat16 al = __float2bfloat16(a - __bfloat162float(ah));
            __nv_bfloat16 cl = __float2bfloat16(c - __bfloat162float(ch));
            __nv_bfloat162 hv; hv.x = ah; hv.y = ch;
            __nv_bfloat162 lv; lv.x = al; lv.y = cl;
            ((__nv_bfloat162*)(dhi + b))[q] = hv;
            ((__nv_bfloat162*)(dlo + b))[q] = lv;
        }
    }
}

// ---------------------------------------------------------------------------
// Fused mma.sync GEMM (128x128 tile = 2 imgs x 2 caps), double-buffered
// cp.async pipeline, + warp-per-pair Sinkhorn.
// 8 warps: wm = wid&1 (m64 block), wn = wid>>1 (n32 block).
// ---------------------------------------------------------------------------
__global__ __launch_bounds__(256, 2)
void wass_mma_kernel(const int* __restrict__ ilens, const int* __restrict__ clens,
                     float* __restrict__ out) {
    extern __shared__ __align__(16) char smem[];
    const uint32_t sb = smem_u32(smem);
    const int tid = threadIdx.x, wid = tid >> 5, lane = tid & 31;
    const int wm = wid & 1, wn = wid >> 1;
    const int i0 = blockIdx.y * 2, j0 = blockIdx.x * 2;

    // ldmatrix per-lane byte offsets within a tile
    const uint32_t aoff = (uint32_t)((wm*64 + (lane & 15)) * RS + ((lane >> 4) & 1) * 16);
    const uint32_t boff = (uint32_t)((wn*32 + (lane & 7) + ((lane >> 4) * 8)) * RS
                                     + ((lane >> 3) & 1) * 16);

    float acc[4][4][4];
#pragma unroll
    for (int mb = 0; mb < 4; mb++)
#pragma unroll
        for (int j = 0; j < 4; j++)
#pragma unroll
            for (int e = 0; e < 4; e++) acc[mb][j][e] = 0.0f;

    // ---- stage loader: chunk ch (32 K-cols) into stage st ----
    auto stage_load = [&](int st, int ch) {
        const int kb = ch * 32;
        const uint32_t base = sb + (uint32_t)(st * STAGE_B);
        for (int t = tid; t < 1024; t += 256) {
            int u = t & 511, mr = u >> 2, q = u & 3, r = mr & 63;
            uint32_t soff = (uint32_t)(mr * RS + q * 16);
            if (t < 512) {
                if (r < RR) {
                    size_t gof = ((size_t)((i0 + (mr >> 6)) * RR + r)) * DD + kb + q * 8;
                    cp16(base + T_AHI + soff, g_Ahi + gof);
                    cp16(base + T_ALO + soff, g_Alo + gof);
                }
            } else {
                if (r < WW) {
                    size_t gof = ((size_t)((j0 + (mr >> 6)) * WW + r)) * DD + kb + q * 8;
                    cp16(base + T_BHI + soff, g_Bhi + gof);
                    cp16(base + T_BLO + soff, g_Blo + gof);
                }
            }
        }
    };

    // ---- pipelined mainloop: 8 chunks, ping-pong stages ----
    stage_load(0, 0);
    CP_COMMIT();
#pragma unroll 1
    for (int ch = 0; ch < 8; ch++) {
        if (ch + 1 < 8) { stage_load((ch + 1) & 1, ch + 1); CP_COMMIT(); }
        if (ch + 1 < 8) { CP_WAIT(1); } else { CP_WAIT(0); }
        __syncthreads();

        const uint32_t stb = sb + (uint32_t)((ch & 1) * STAGE_B);
        const uint32_t a_hi = stb + T_AHI + aoff, a_lo = stb + T_ALO + aoff;
        const uint32_t b_hi = stb + T_BHI + boff, b_lo = stb + T_BLO + boff;
#pragma unroll
        for (int ks = 0; ks < 2; ks++) {
            const uint32_t ko = (uint32_t)(ks * 32);
            uint32_t ah[4][4], al[4][4], bb[2][4];
#pragma unroll
            for (int mb = 0; mb < 4; mb++) {
                LDSM_X4(ah[mb], a_hi + (uint32_t)(mb * 16 * RS) + ko);
                LDSM_X4(al[mb], a_lo + (uint32_t)(mb * 16 * RS) + ko);
            }
#pragma unroll
            for (int nb = 0; nb < 2; nb++)
                LDSM_X4(bb[nb], b_hi + (uint32_t)(nb * 16 * RS) + ko);
            // hh + lh (share B-hi fragments)
#pragma unroll
            for (int mb = 0; mb < 4; mb++)
#pragma unroll
                for (int j = 0; j < 4; j++) {
                    MMA16816(acc[mb][j], ah[mb], bb[j >> 1][(j & 1) * 2], bb[j >> 1][(j & 1) * 2 + 1]);
                    MMA16816(acc[mb][j], al[mb], bb[j >> 1][(j & 1) * 2], bb[j >> 1][(j & 1) * 2 + 1]);
                }
            // hl (reload B-lo into bb)
#pragma unroll
            for (int nb = 0; nb < 2; nb++)
                LDSM_X4(bb[nb], b_lo + (uint32_t)(nb * 16 * RS) + ko);
#pragma unroll
            for (int mb = 0; mb < 4; mb++)
#pragma unroll
                for (int j = 0; j < 4; j++)
                    MMA16816(acc[mb][j], ah[mb], bb[j >> 1][(j & 1) * 2], bb[j >> 1][(j & 1) * 2 + 1]);
        }
        __syncthreads();   // all reads of this stage done before it is refilled
    }

    // ---- epilogue: C fragments -> per-pair S blocks (WPAD layout) ----
    {
        float* Sb = (float*)smem;
        const int gr = lane >> 2, tg = lane & 3;
        const int cap = wn >> 1, wbase = (wn & 1) * 32;
#pragma unroll
        for (int mb = 0; mb < 3; mb++) {          // mb=3 -> rows>=48, all masked
#pragma unroll
            for (int j = 0; j < 4; j++) {
                int w0 = wbase + j * 8 + 2 * tg;
#pragma unroll
                for (int e = 0; e < 4; e++) {
                    int r = mb * 16 + gr + ((e >> 1) ? 8 : 0);
                    int w = w0 + (e & 1);
                    if (r < RR && w < WW)
                        Sb[((wm * 2 + cap) * RR + r) * WPAD + w] = acc[mb][j][e];
                }
            }
        }
    }
    __syncthreads();

    // ---- Sinkhorn: warp p handles pair (i0 + (p>>1), j0 + (p&1)) ----
    if (wid < 4) {
        const int i = i0 + (wid >> 1);
        const int j = j0 + (wid & 1);
        const int nr = ilens[i];
        const int nw = clens[j];
        const float invr = 1.0f / (float)nr;
        const float invw = 1.0f / (float)nw;
        float* S = (float*)smem + wid * PAIR_F;
        float* P = (float*)smem + SM_P_F + wid * PAIR_F;
        const int c0 = lane, c1 = lane + 32;
        const bool v1 = (c1 < WW);

        float loc = 0.0f;
#pragma unroll 4
        for (int r = 0; r < RR; r++) {
            float p0 = 0.0f, p1 = 0.0f;
            if (r < nr && c0 < nw) p0 = __expf(20.0f * (S[r * WPAD + c0] - 1.0f));
            P[r * WPAD + c0] = p0;
            if (v1) {
                if (r < nr && c1 < nw) p1 = __expf(20.0f * (S[r * WPAD + c1] - 1.0f));
                P[r * WPAD + c1] = p1;
            }
            loc += p0 + p1;
        }
#pragma unroll
        for (int o = 16; o; o >>= 1) loc += __shfl_xor_sync(0xffffffffu, loc, o);
        float sc = 1.0f / (loc + 1e-6f);
#pragma unroll 4
        for (int r = 0; r < RR; r++) {
            P[r * WPAD + c0] *= sc;
            if (v1) P[r * WPAD + c1] *= sc;
        }

#pragma unroll 1
        for (int it = 0; it < 3; it++) {
#pragma unroll 2
            for (int r = 0; r < RR; r++) {
                float t = P[r * WPAD + c0] + (v1 ? P[r * WPAD + c1] : 0.0f);
#pragma unroll
                for (int o = 16; o; o >>= 1) t += __shfl_xor_sync(0xffffffffu, t, o);
                float f = ((r < nr) ? invr : 0.0f) / (t + 1e-6f);
                P[r * WPAD + c0] *= f;
                if (v1) P[r * WPAD + c1] *= f;
            }
            float v0s = 0.0f, v1s = 0.0f;
#pragma unroll 4
            for (int r = 0; r < RR; r++) {
                v0s += P[r * WPAD + c0];
                if (v1) v1s += P[r * WPAD + c1];
            }
            float f0 = ((c0 < nw) ? invw : 0.0f) / (v0s + 1e-6f);
            float f1 = v1 ? (((c1 < nw) ? invw : 0.0f) / (v1s + 1e-6f)) : 0.0f;
#pragma unroll 4
            for (int r = 0; r < RR; r++) {
                P[r * WPAD + c0] *= f0;
                if (v1) P[r * WPAD + c1] *= f1;
            }
        }

        float fin = 0.0f;
#pragma unroll 4
        for (int r = 0; r < RR; r++) {
            fin += S[r * WPAD + c0] * P[r * WPAD + c0];
            if (v1) fin += S[r * WPAD + c1] * P[r * WPAD + c1];
        }
#pragma unroll
        for (int o = 16; o; o >>= 1) fin += __shfl_xor_sync(0xffffffffu, fin, o);
        if (lane == 0) out[i * NJ + j] = fin;
    }
}

// ---------------------------------------------------------------------------
extern "C" void kernel_launch(void* const* d_in, const int* in_sizes, int n_in,
                              void* d_out, int out_size) {
    const float* imgs  = (const float*)d_in[0];
    const float* caps  = (const float*)d_in[1];
    const int*   ilens = (const int*)d_in[2];
    const int*   clens = (const int*)d_in[3];
    float* out = (float*)d_out;

    cudaFuncSetAttribute(wass_mma_kernel,
                         cudaFuncAttributeMaxDynamicSharedMemorySize, SMEM_TOTAL);

    const int total_rows = NI * RR + NJ * WW;   // 11008 rows, 1 warp each
    int nblocks = (total_rows + 7) / 8;
    prep_kernel<<<nblocks, 256>>>(imgs, caps);

    dim3 grid(NJ / 2, NI / 2);                  // 64 x 64 tiles
    wass_mma_kernel<<<grid, 256, SMEM_TOTAL>>>(ilens, clens, out);
}

// round 13
// speedup vs baseline: 1.3280x; 1.3280x over previous
#include <cuda_runtime.h>
#include <cuda_bf16.h>
#include <math.h>
#include <stdint.h>

#define RR 36
#define WW 50
#define DD 256
#define NI 128
#define NJ 128
#define MIMG 3                 /* images packed per 128-row tile (108 rows) */
#define MROWS (MIMG * RR)      /* 108 */
#define GY 43                  /* ceil(128/3) */

// ---------------- split bf16 global scratch (allocation-free) --------------
__device__ __align__(16) __nv_bfloat16 g_Ahi[NI * RR * DD];
__device__ __align__(16) __nv_bfloat16 g_Alo[NI * RR * DD];
__device__ __align__(16) __nv_bfloat16 g_Bhi[NJ * WW * DD];
__device__ __align__(16) __nv_bfloat16 g_Blo[NJ * WW * DD];

// ---------------- SMEM layout (bytes) --------------------------------------
// GEMM: K-chunk = 64 cols bf16 = 128B + 16B pad -> 144B row stride.
#define RS      144
#define TILE_B  (128 * RS)           /* 18432 */
#define T_AHI   0
#define T_ALO   TILE_B
#define T_BHI   (2 * TILE_B)
#define T_BLO   (3 * TILE_B)
// Sinkhorn aliases the GEMM tiles: 6 pairs, S+P
#define WPAD    53
#define PAIR_F  (RR * WPAD)          /* 1908 floats */
#define SM_P_F  (6 * PAIR_F)
#define SMEM_TOTAL 91584             /* max(4*TILE_B=73728, 2*6*PAIR_F*4) */

// ---------------- PTX helpers (base-target instructions only) ---------------
__device__ __forceinline__ uint32_t smem_u32(const void* p) {
    uint32_t a;
    asm("{ .reg .u64 t; cvta.to.shared.u64 t, %1; cvt.u32.u64 %0, t; }"
        : "=r"(a) : "l"(p));
    return a;
}
__device__ __forceinline__ void cp16(uint32_t s, const void* g) {
    asm volatile("cp.async.ca.shared.global [%0], [%1], 16;" :: "r"(s), "l"(g));
}
#define CP_COMMIT() asm volatile("cp.async.commit_group;" ::: "memory")
#define CP_WAIT0()  asm volatile("cp.async.wait_group 0;" ::: "memory")

#define LDSM_X4(r, addr)                                                      \
    asm volatile("ldmatrix.sync.aligned.m8n8.x4.shared.b16 {%0,%1,%2,%3}, [%4];" \
                 : "=r"((r)[0]), "=r"((r)[1]), "=r"((r)[2]), "=r"((r)[3])     \
                 : "r"(addr))

#define MMA16816(d, a, b0, b1)                                                \
    asm volatile("mma.sync.aligned.m16n8k16.row.col.f32.bf16.bf16.f32 "       \
                 "{%0,%1,%2,%3}, {%4,%5,%6,%7}, {%8,%9}, {%0,%1,%2,%3};"      \
                 : "+f"((d)[0]), "+f"((d)[1]), "+f"((d)[2]), "+f"((d)[3])     \
                 : "r"((a)[0]), "r"((a)[1]), "r"((a)[2]), "r"((a)[3]),        \
                   "r"(b0), "r"(b1))

// ---------------------------------------------------------------------------
// Prep: L2-normalize each 256-d row, emit split bf16 (hi, lo). 1 warp/row.
// ---------------------------------------------------------------------------
__global__ __launch_bounds__(256)
void prep_kernel(const float* __restrict__ imgs, const float* __restrict__ caps) {
    int gw   = blockIdx.x * 8 + (threadIdx.x >> 5);
    int lane = threadIdx.x & 31;
    const int na = NI * RR;
    const float* src;
    __nv_bfloat16 *dhi, *dlo;
    if (gw < na) {
        src = imgs + (size_t)gw * DD;
        dhi = g_Ahi + (size_t)gw * DD;
        dlo = g_Alo + (size_t)gw * DD;
    } else {
        int g2 = gw - na;
        if (g2 >= NJ * WW) return;
        src = caps + (size_t)g2 * DD;
        dhi = g_Bhi + (size_t)g2 * DD;
        dlo = g_Blo + (size_t)g2 * DD;
    }
    float4 x0 = ((const float4*)src)[lane];
    float4 x1 = ((const float4*)src)[lane + 32];
    float ss = x0.x*x0.x + x0.y*x0.y + x0.z*x0.z + x0.w*x0.w
             + x1.x*x1.x + x1.y*x1.y + x1.z*x1.z + x1.w*x1.w;
#pragma unroll
    for (int o = 16; o; o >>= 1) ss += __shfl_xor_sync(0xffffffffu, ss, o);
    float sc = 1.0f / fmaxf(sqrtf(ss), 1e-8f);
    float xs[8] = { x0.x*sc, x0.y*sc, x0.z*sc, x0.w*sc,
                    x1.x*sc, x1.y*sc, x1.z*sc, x1.w*sc };
#pragma unroll
    for (int h = 0; h < 2; h++) {
        int b = h * 128 + 4 * lane;
#pragma unroll
        for (int q = 0; q < 2; q++) {
            float a = xs[h*4 + q*2], c = xs[h*4 + q*2 + 1];
            __nv_bfloat16 ah = __float2bfloat16(a);
            __nv_bfloat16 ch = __float2bfloat16(c);
            __nv_bfloat16 al = __float2bfloat16(a - __bfloat162float(ah));
            __nv_bfloat16 cl = __float2bfloat16(c - __bfloat162float(ch));
            __nv_bfloat162 hv; hv.x = ah; hv.y = ch;
            __nv_bfloat162 lv; lv.x = al; lv.y = cl;
            ((__nv_bfloat162*)(dhi + b))[q] = hv;
            ((__nv_bfloat162*)(dlo + b))[q] = lv;
        }
    }
}

// ---------------------------------------------------------------------------
// Fused mma.sync GEMM: tile = 3 imgs (108 rows) x 2 caps (100 cols),
// reordered MMA sweeps, + warp-per-pair Sinkhorn (6 pairs).
// 8 warps: wm = wid&1 (m64 block), wn = wid>>1 (n32 block).
// ---------------------------------------------------------------------------
__global__ __launch_bounds__(256, 2)
void wass_mma_kernel(const int* __restrict__ ilens, const int* __restrict__ clens,
                     float* __restrict__ out) {
    extern __shared__ __align__(16) char smem[];
    const uint32_t sb = smem_u32(smem);
    const int tid = threadIdx.x, wid = tid >> 5, lane = tid & 31;
    const int wm = wid & 1, wn = wid >> 1;
    const int i0 = blockIdx.y * MIMG, j0 = blockIdx.x * 2;

    // ldmatrix per-lane byte offsets within a tile
    const uint32_t aoff = (uint32_t)((wm*64 + (lane & 15)) * RS + ((lane >> 4) & 1) * 16);
    const uint32_t boff = (uint32_t)((wn*32 + (lane & 7) + ((lane >> 4) * 8)) * RS
                                     + ((lane >> 3) & 1) * 16);
    const uint32_t a_hi = sb + T_AHI + aoff, a_lo = sb + T_ALO + aoff;
    const uint32_t b_hi = sb + T_BHI + boff, b_lo = sb + T_BLO + boff;

    float acc[4][4][4];
#pragma unroll
    for (int mb = 0; mb < 4; mb++)
#pragma unroll
        for (int j = 0; j < 4; j++)
#pragma unroll
            for (int e = 0; e < 4; e++) acc[mb][j][e] = 0.0f;

    for (int ch = 0; ch < 4; ch++) {
        const int kb = ch * 64;
        if (ch) __syncthreads();            // prior chunk fully consumed
        // A: 108 real rows (3 imgs x 36), 8 quads of 16B each
        for (int t = tid; t < 1024; t += 256) {
            int mr = t >> 3, q = t & 7;
            if (mr < MROWS) {
                int img = mr / RR, r = mr - img * RR;
                int gi = i0 + img;
                if (gi < NI) {
                    size_t gof = ((size_t)(gi * RR + r)) * DD + kb + q * 8;
                    uint32_t soff = (uint32_t)(mr * RS + q * 16);
                    cp16(sb + T_AHI + soff, g_Ahi + gof);
                    cp16(sb + T_ALO + soff, g_Alo + gof);
                }
            }
        }
        // B: 2 caps x 50 rows in 2x64 blocks
        for (int t = tid; t < 1024; t += 256) {
            int mr = t >> 3, q = t & 7, r = mr & 63;
            if (r < WW) {
                size_t gof = ((size_t)((j0 + (mr >> 6)) * WW + r)) * DD + kb + q * 8;
                uint32_t soff = (uint32_t)(mr * RS + q * 16);
                cp16(sb + T_BHI + soff, g_Bhi + gof);
                cp16(sb + T_BLO + soff, g_Blo + gof);
            }
        }
        CP_COMMIT(); CP_WAIT0();
        __syncthreads();

#pragma unroll
        for (int ks = 0; ks < 4; ks++) {
            const uint32_t ko = (uint32_t)(ks * 32);
            uint32_t ah[4][4], al[4][4], bb[2][4];
#pragma unroll
            for (int mb = 0; mb < 4; mb++) {
                LDSM_X4(ah[mb], a_hi + (uint32_t)(mb * 16 * RS) + ko);
                LDSM_X4(al[mb], a_lo + (uint32_t)(mb * 16 * RS) + ko);
            }
#pragma unroll
            for (int nb = 0; nb < 2; nb++)
                LDSM_X4(bb[nb], b_hi + (uint32_t)(nb * 16 * RS) + ko);
            // hh sweep (16 independent MMAs)
#pragma unroll
            for (int mb = 0; mb < 4; mb++)
#pragma unroll
                for (int j = 0; j < 4; j++)
                    MMA16816(acc[mb][j], ah[mb], bb[j >> 1][(j & 1) * 2], bb[j >> 1][(j & 1) * 2 + 1]);
            // lh sweep (RAW distance 16 to hh sweep)
#pragma unroll
            for (int mb = 0; mb < 4; mb++)
#pragma unroll
                for (int j = 0; j < 4; j++)
                    MMA16816(acc[mb][j], al[mb], bb[j >> 1][(j & 1) * 2], bb[j >> 1][(j & 1) * 2 + 1]);
            // reload B-lo, hl sweep
#pragma unroll
            for (int nb = 0; nb < 2; nb++)
                LDSM_X4(bb[nb], b_lo + (uint32_t)(nb * 16 * RS) + ko);
#pragma unroll
            for (int mb = 0; mb < 4; mb++)
#pragma unroll
                for (int j = 0; j < 4; j++)
                    MMA16816(acc[mb][j], ah[mb], bb[j >> 1][(j & 1) * 2], bb[j >> 1][(j & 1) * 2 + 1]);
        }
    }
    __syncthreads();   // all ldmatrix reads done before aliasing S over tiles

    // ---- epilogue: C fragments -> per-pair S blocks (WPAD layout) ----
    {
        float* Sb = (float*)smem;
        const int gr = lane >> 2, tg = lane & 3;
        const int cap = wn >> 1, wbase = (wn & 1) * 32;
#pragma unroll
        for (int mb = 0; mb < 4; mb++) {
#pragma unroll
            for (int j = 0; j < 4; j++) {
                int w0 = wbase + j * 8 + 2 * tg;
#pragma unroll
                for (int e = 0; e < 4; e++) {
                    int row = wm * 64 + mb * 16 + gr + ((e >> 1) ? 8 : 0);
                    int w = w0 + (e & 1);
                    if (row < MROWS && w < WW) {
                        int img = row / RR, rr = row - img * RR;
                        if (i0 + img < NI)
                            Sb[((img * 2 + cap) * RR + rr) * WPAD + w] = acc[mb][j][e];
                    }
                }
            }
        }
    }
    __syncthreads();

    // ---- Sinkhorn: warp p handles pair (i0 + (p>>1), j0 + (p&1)) ----
    if (wid < 6 && i0 + (wid >> 1) < NI) {
        const int i = i0 + (wid >> 1);
        const int j = j0 + (wid & 1);
        const int nr = ilens[i];
        const int nw = clens[j];
        const float invr = 1.0f / (float)nr;
        const float invw = 1.0f / (float)nw;
        float* S = (float*)smem + wid * PAIR_F;
        float* P = (float*)smem + SM_P_F + wid * PAIR_F;
        const int c0 = lane, c1 = lane + 32;
        const bool v1 = (c1 < WW);

        float loc = 0.0f;
#pragma unroll 4
        for (int r = 0; r < RR; r++) {
            float p0 = 0.0f, p1 = 0.0f;
            if (r < nr && c0 < nw) p0 = __expf(20.0f * (S[r * WPAD + c0] - 1.0f));
            P[r * WPAD + c0] = p0;
            if (v1) {
                if (r < nr && c1 < nw) p1 = __expf(20.0f * (S[r * WPAD + c1] - 1.0f));
                P[r * WPAD + c1] = p1;
            }
            loc += p0 + p1;
        }
#pragma unroll
        for (int o = 16; o; o >>= 1) loc += __shfl_xor_sync(0xffffffffu, loc, o);
        float sc = 1.0f / (loc + 1e-6f);
#pragma unroll 4
        for (int r = 0; r < RR; r++) {
            P[r * WPAD + c0] *= sc;
            if (v1) P[r * WPAD + c1] *= sc;
        }

#pragma unroll 1
        for (int it = 0; it < 3; it++) {
#pragma unroll 2
            for (int r = 0; r < RR; r++) {
                float t = P[r * WPAD + c0] + (v1 ? P[r * WPAD + c1] : 0.0f);
#pragma unroll
                for (int o = 16; o; o >>= 1) t += __shfl_xor_sync(0xffffffffu, t, o);
                float f = ((r < nr) ? invr : 0.0f) / (t + 1e-6f);
                P[r * WPAD + c0] *= f;
                if (v1) P[r * WPAD + c1] *= f;
            }
            float v0s = 0.0f, v1s = 0.0f;
#pragma unroll 4
            for (int r = 0; r < RR; r++) {
                v0s += P[r * WPAD + c0];
                if (v1) v1s += P[r * WPAD + c1];
            }
            float f0 = ((c0 < nw) ? invw : 0.0f) / (v0s + 1e-6f);
            float f1 = v1 ? (((c1 < nw) ? invw : 0.0f) / (v1s + 1e-6f)) : 0.0f;
#pragma unroll 4
            for (int r = 0; r < RR; r++) {
                P[r * WPAD + c0] *= f0;
                if (v1) P[r * WPAD + c1] *= f1;
            }
        }

        float fin = 0.0f;
#pragma unroll 4
        for (int r = 0; r < RR; r++) {
            fin += S[r * WPAD + c0] * P[r * WPAD + c0];
            if (v1) fin += S[r * WPAD + c1] * P[r * WPAD + c1];
        }
#pragma unroll
        for (int o = 16; o; o >>= 1) fin += __shfl_xor_sync(0xffffffffu, fin, o);
        if (lane == 0) out[i * NJ + j] = fin;
    }
}

// ---------------------------------------------------------------------------
extern "C" void kernel_launch(void* const* d_in, const int* in_sizes, int n_in,
                              void* d_out, int out_size) {
    const float* imgs  = (const float*)d_in[0];
    const float* caps  = (const float*)d_in[1];
    const int*   ilens = (const int*)d_in[2];
    const int*   clens = (const int*)d_in[3];
    float* out = (float*)d_out;

    cudaFuncSetAttribute(wass_mma_kernel,
                         cudaFuncAttributeMaxDynamicSharedMemorySize, SMEM_TOTAL);

    const int total_rows = NI * RR + NJ * WW;   // 11008 rows, 1 warp each
    int nblocks = (total_rows + 7) / 8;
    prep_kernel<<<nblocks, 256>>>(imgs, caps);

    dim3 grid(NJ / 2, GY);                      // 64 x 43 tiles
    wass_mma_kernel<<<grid, 256, SMEM_TOTAL>>>(ilens, clens, out);
}

// round 16
// speedup vs baseline: 1.8274x; 1.3761x over previous
#include <cuda_runtime.h>
#include <cuda_bf16.h>
#include <math.h>
#include <stdint.h>

#define RR 36
#define WW 50
#define DD 256
#define NI 128
#define NJ 128
#define MM (NI * RR)           /* 4608 */
#define NN (NJ * WW)           /* 6400 */

// ---------------- global scratch (allocation-free) -------------------------
__device__ __align__(16) __nv_bfloat16 g_Ahi[MM * DD];
__device__ __align__(16) __nv_bfloat16 g_Alo[MM * DD];
__device__ __align__(16) __nv_bfloat16 g_Bhi[NN * DD];
__device__ __align__(16) __nv_bfloat16 g_Blo[NN * DD];
__device__ __align__(16) float g_C[(size_t)MM * NN];   /* 118 MB */

// ---------------- SMEM layout (bytes), GEMM kernel -------------------------
#define RS      144              /* 64 bf16 cols = 128B + 16B pad */
#define TILE_B  (128 * RS)       /* 18432 */
#define T_AHI   0
#define T_ALO   TILE_B
#define T_BHI   (2 * TILE_B)
#define T_BLO   (3 * TILE_B)
#define SMEM_TOTAL (4 * TILE_B)  /* 73728 */

// ---------------- PTX helpers (base-target instructions only) ---------------
__device__ __forceinline__ uint32_t smem_u32(const void* p) {
    uint32_t a;
    asm("{ .reg .u64 t; cvta.to.shared.u64 t, %1; cvt.u32.u64 %0, t; }"
        : "=r"(a) : "l"(p));
    return a;
}
__device__ __forceinline__ void cp16(uint32_t s, const void* g) {
    asm volatile("cp.async.ca.shared.global [%0], [%1], 16;" :: "r"(s), "l"(g));
}
#define CP_COMMIT() asm volatile("cp.async.commit_group;" ::: "memory")
#define CP_WAIT0()  asm volatile("cp.async.wait_group 0;" ::: "memory")

#define LDSM_X4(r, addr)                                                      \
    asm volatile("ldmatrix.sync.aligned.m8n8.x4.shared.b16 {%0,%1,%2,%3}, [%4];" \
                 : "=r"((r)[0]), "=r"((r)[1]), "=r"((r)[2]), "=r"((r)[3])     \
                 : "r"(addr))

#define MMA16816(d, a, b0, b1)                                                \
    asm volatile("mma.sync.aligned.m16n8k16.row.col.f32.bf16.bf16.f32 "       \
                 "{%0,%1,%2,%3}, {%4,%5,%6,%7}, {%8,%9}, {%0,%1,%2,%3};"      \
                 : "+f"((d)[0]), "+f"((d)[1]), "+f"((d)[2]), "+f"((d)[3])     \
                 : "r"((a)[0]), "r"((a)[1]), "r"((a)[2]), "r"((a)[3]),        \
                   "r"(b0), "r"(b1))

// ---------------------------------------------------------------------------
// Prep: L2-normalize each 256-d row, emit split bf16 (hi, lo). 1 warp/row.
// ---------------------------------------------------------------------------
__global__ __launch_bounds__(256)
void prep_kernel(const float* __restrict__ imgs, const float* __restrict__ caps) {
    int gw   = blockIdx.x * 8 + (threadIdx.x >> 5);
    int lane = threadIdx.x & 31;
    const float* src;
    __nv_bfloat16 *dhi, *dlo;
    if (gw < MM) {
        src = imgs + (size_t)gw * DD;
        dhi = g_Ahi + (size_t)gw * DD;
        dlo = g_Alo + (size_t)gw * DD;
    } else {
        int g2 = gw - MM;
        if (g2 >= NN) return;
        src = caps + (size_t)g2 * DD;
        dhi = g_Bhi + (size_t)g2 * DD;
        dlo = g_Blo + (size_t)g2 * DD;
    }
    float4 x0 = ((const float4*)src)[lane];
    float4 x1 = ((const float4*)src)[lane + 32];
    float ss = x0.x*x0.x + x0.y*x0.y + x0.z*x0.z + x0.w*x0.w
             + x1.x*x1.x + x1.y*x1.y + x1.z*x1.z + x1.w*x1.w;
#pragma unroll
    for (int o = 16; o; o >>= 1) ss += __shfl_xor_sync(0xffffffffu, ss, o);
    float sc = 1.0f / fmaxf(sqrtf(ss), 1e-8f);
    float xs[8] = { x0.x*sc, x0.y*sc, x0.z*sc, x0.w*sc,
                    x1.x*sc, x1.y*sc, x1.z*sc, x1.w*sc };
#pragma unroll
    for (int h = 0; h < 2; h++) {
        int b = h * 128 + 4 * lane;
#pragma unroll
        for (int q = 0; q < 2; q++) {
            float a = xs[h*4 + q*2], c = xs[h*4 + q*2 + 1];
            __nv_bfloat16 ah = __float2bfloat16(a);
            __nv_bfloat16 ch = __float2bfloat16(c);
            __nv_bfloat16 al = __float2bfloat16(a - __bfloat162float(ah));
            __nv_bfloat16 cl = __float2bfloat16(c - __bfloat162float(ch));
            __nv_bfloat162 hv; hv.x = ah; hv.y = ch;
            __nv_bfloat162 lv; lv.x = al; lv.y = cl;
            ((__nv_bfloat162*)(dhi + b))[q] = hv;
            ((__nv_bfloat162*)(dlo + b))[q] = lv;
        }
    }
}

// ---------------------------------------------------------------------------
// Dense GEMM: C[4608 x 6400] = A * B^T, split-bf16 (hh + lh + hl), fp32 acc.
// 128x128 CTA tile, 8 warps (wm = wid&1 -> m64, wn = wid>>1 -> n32).
// No padding, no guards: every row/col is real.
// ---------------------------------------------------------------------------
__global__ __launch_bounds__(256, 2)
void gemm_kernel() {
    extern __shared__ __align__(16) char smem[];
    const uint32_t sb = smem_u32(smem);
    const int tid = threadIdx.x, wid = tid >> 5, lane = tid & 31;
    const int wm = wid & 1, wn = wid >> 1;
    const int m0 = blockIdx.y * 128, n0 = blockIdx.x * 128;

    const uint32_t aoff = (uint32_t)((wm*64 + (lane & 15)) * RS + ((lane >> 4) & 1) * 16);
    const uint32_t boff = (uint32_t)((wn*32 + (lane & 7) + ((lane >> 4) * 8)) * RS
                                     + ((lane >> 3) & 1) * 16);
    const uint32_t a_hi = sb + T_AHI + aoff, a_lo = sb + T_ALO + aoff;
    const uint32_t b_hi = sb + T_BHI + boff, b_lo = sb + T_BLO + boff;

    float acc[4][4][4];
#pragma unroll
    for (int mb = 0; mb < 4; mb++)
#pragma unroll
        for (int j = 0; j < 4; j++)
#pragma unroll
            for (int e = 0; e < 4; e++) acc[mb][j][e] = 0.0f;

    for (int ch = 0; ch < 4; ch++) {
        const int kb = ch * 64;
        if (ch) __syncthreads();
        // guard-free cooperative loads: 1024 positions x 4 matrices
        for (int t = tid; t < 1024; t += 256) {
            int mr = t >> 3, q = t & 7;
            uint32_t soff = (uint32_t)(mr * RS + q * 16);
            size_t ga = ((size_t)(m0 + mr)) * DD + kb + q * 8;
            size_t gb = ((size_t)(n0 + mr)) * DD + kb + q * 8;
            cp16(sb + T_AHI + soff, g_Ahi + ga);
            cp16(sb + T_ALO + soff, g_Alo + ga);
            cp16(sb + T_BHI + soff, g_Bhi + gb);
            cp16(sb + T_BLO + soff, g_Blo + gb);
        }
        CP_COMMIT(); CP_WAIT0();
        __syncthreads();

#pragma unroll
        for (int ks = 0; ks < 4; ks++) {
            const uint32_t ko = (uint32_t)(ks * 32);
            uint32_t ah[4][4], al[4][4], bb[2][4];
#pragma unroll
            for (int mb = 0; mb < 4; mb++) {
                LDSM_X4(ah[mb], a_hi + (uint32_t)(mb * 16 * RS) + ko);
                LDSM_X4(al[mb], a_lo + (uint32_t)(mb * 16 * RS) + ko);
            }
#pragma unroll
            for (int nb = 0; nb < 2; nb++)
                LDSM_X4(bb[nb], b_hi + (uint32_t)(nb * 16 * RS) + ko);
            // hh sweep
#pragma unroll
            for (int mb = 0; mb < 4; mb++)
#pragma unroll
                for (int j = 0; j < 4; j++)
                    MMA16816(acc[mb][j], ah[mb], bb[j >> 1][(j & 1) * 2], bb[j >> 1][(j & 1) * 2 + 1]);
            // lh sweep
#pragma unroll
            for (int mb = 0; mb < 4; mb++)
#pragma unroll
                for (int j = 0; j < 4; j++)
                    MMA16816(acc[mb][j], al[mb], bb[j >> 1][(j & 1) * 2], bb[j >> 1][(j & 1) * 2 + 1]);
            // hl sweep
#pragma unroll
            for (int nb = 0; nb < 2; nb++)
                LDSM_X4(bb[nb], b_lo + (uint32_t)(nb * 16 * RS) + ko);
#pragma unroll
            for (int mb = 0; mb < 4; mb++)
#pragma unroll
                for (int j = 0; j < 4; j++)
                    MMA16816(acc[mb][j], ah[mb], bb[j >> 1][(j & 1) * 2], bb[j >> 1][(j & 1) * 2 + 1]);
        }
    }

    // epilogue: direct float2 stores to C (no sync needed, no smem reuse)
    {
        const int gr = lane >> 2, tg = lane & 3;
#pragma unroll
        for (int mb = 0; mb < 4; mb++) {
            int r0 = m0 + wm * 64 + mb * 16 + gr;
#pragma unroll
            for (int j = 0; j < 4; j++) {
                int c = n0 + wn * 32 + j * 8 + 2 * tg;
                float2 v0 = { acc[mb][j][0], acc[mb][j][1] };
                float2 v1 = { acc[mb][j][2], acc[mb][j][3] };
                *(float2*)&g_C[(size_t)r0 * NN + c]       = v0;
                *(float2*)&g_C[(size_t)(r0 + 8) * NN + c] = v1;
            }
        }
    }
}

// ---------------------------------------------------------------------------
// Sinkhorn: 1 warp per (i,j) pair, P in registers (lane owns cols lane, lane+32),
// S read from g_C (L2-hot). 8 warps per CTA, no smem.
// ---------------------------------------------------------------------------
__global__ __launch_bounds__(256)
void sink_kernel(const int* __restrict__ ilens, const int* __restrict__ clens,
                 float* __restrict__ out) {
    const int p = blockIdx.x * 8 + (threadIdx.x >> 5);
    const int lane = threadIdx.x & 31;
    const int i = p >> 7, j = p & 127;
    const int nr = ilens[i];
    const int nw = clens[j];
    const float invr = 1.0f / (float)nr;
    const float invw = 1.0f / (float)nw;
    const float* Srow = g_C + (size_t)(i * RR) * NN + j * WW;
    const int c0 = lane, c1 = lane + 32;
    const bool v1 = (c1 < WW);

    float P0[RR], P1[RR];
    float loc = 0.0f;
#pragma unroll
    for (int r = 0; r < RR; r++) {
        float p0 = 0.0f, p1 = 0.0f;
        if (r < nr && c0 < nw) p0 = __expf(20.0f * (Srow[(size_t)r * NN + c0] - 1.0f));
        if (v1 && r < nr && c1 < nw) p1 = __expf(20.0f * (Srow[(size_t)r * NN + c1] - 1.0f));
        P0[r] = p0; P1[r] = p1;
        loc += p0 + p1;
    }
#pragma unroll
    for (int o = 16; o; o >>= 1) loc += __shfl_xor_sync(0xffffffffu, loc, o);
    float sc = 1.0f / (loc + 1e-6f);
#pragma unroll
    for (int r = 0; r < RR; r++) { P0[r] *= sc; P1[r] *= sc; }

#pragma unroll 1
    for (int it = 0; it < 3; it++) {
#pragma unroll
        for (int r = 0; r < RR; r++) {
            float t = P0[r] + P1[r];
#pragma unroll
            for (int o = 16; o; o >>= 1) t += __shfl_xor_sync(0xffffffffu, t, o);
            float f = ((r < nr) ? invr : 0.0f) / (t + 1e-6f);
            P0[r] *= f; P1[r] *= f;
        }
        float v0s = 0.0f, v1s = 0.0f;
#pragma unroll
        for (int r = 0; r < RR; r++) { v0s += P0[r]; v1s += P1[r]; }
        float f0 = ((c0 < nw) ? invw : 0.0f) / (v0s + 1e-6f);
        float f1 = ((v1 && c1 < nw) ? invw : 0.0f) / (v1s + 1e-6f);
#pragma unroll
        for (int r = 0; r < RR; r++) { P0[r] *= f0; P1[r] *= f1; }
    }

    float fin = 0.0f;
#pragma unroll
    for (int r = 0; r < RR; r++) {
        fin += Srow[(size_t)r * NN + c0] * P0[r];
        if (v1) fin += Srow[(size_t)r * NN + c1] * P1[r];
    }
#pragma unroll
    for (int o = 16; o; o >>= 1) fin += __shfl_xor_sync(0xffffffffu, fin, o);
    if (lane == 0) out[i * NJ + j] = fin;
}

// ---------------------------------------------------------------------------
extern "C" void kernel_launch(void* const* d_in, const int* in_sizes, int n_in,
                              void* d_out, int out_size) {
    const float* imgs  = (const float*)d_in[0];
    const float* caps  = (const float*)d_in[1];
    const int*   ilens = (const int*)d_in[2];
    const int*   clens = (const int*)d_in[3];
    float* out = (float*)d_out;

    cudaFuncSetAttribute(gemm_kernel,
                         cudaFuncAttributeMaxDynamicSharedMemorySize, SMEM_TOTAL);

    const int total_rows = MM + NN;             // 11008 rows, 1 warp each
    int nblocks = (total_rows + 7) / 8;
    prep_kernel<<<nblocks, 256>>>(imgs, caps);

    dim3 ggrid(NN / 128, MM / 128);             // 50 x 36 = 1800 CTAs
    gemm_kernel<<<ggrid, 256, SMEM_TOTAL>>>();

    sink_kernel<<<(NI * NJ) / 8, 256>>>(ilens, clens, out);
}

// round 17
// speedup vs baseline: 2.1184x; 1.1592x over previous
#include <cuda_runtime.h>
#include <cuda_bf16.h>
#include <math.h>
#include <stdint.h>

#define RR 36
#define WW 50
#define DD 256
#define NI 128
#define NJ 128
#define MM (NI * RR)           /* 4608 */
#define NN (NJ * WW)           /* 6400 */

// ---------------- global scratch (allocation-free) -------------------------
__device__ __align__(16) __nv_bfloat16 g_Ahi[MM * DD];
__device__ __align__(16) __nv_bfloat16 g_Alo[MM * DD];
__device__ __align__(16) __nv_bfloat16 g_Bhi[NN * DD];
__device__ __align__(16) __nv_bfloat16 g_Blo[NN * DD];
__device__ __align__(16) float g_C[(size_t)MM * NN];   /* 118 MB */

// ---------------- SMEM layout (bytes), GEMM kernel -------------------------
#define RS      144              /* 64 bf16 cols = 128B + 16B pad */
#define TILE_B  (128 * RS)       /* 18432 */
#define T_AHI   0
#define T_ALO   TILE_B
#define T_BHI   (2 * TILE_B)
#define T_BLO   (3 * TILE_B)
#define SMEM_TOTAL (4 * TILE_B)  /* 73728 */

// ---------------- PTX helpers (base-target instructions only) ---------------
__device__ __forceinline__ uint32_t smem_u32(const void* p) {
    uint32_t a;
    asm("{ .reg .u64 t; cvta.to.shared.u64 t, %1; cvt.u32.u64 %0, t; }"
        : "=r"(a) : "l"(p));
    return a;
}
__device__ __forceinline__ void cp16(uint32_t s, const void* g) {
    asm volatile("cp.async.ca.shared.global [%0], [%1], 16;" :: "r"(s), "l"(g));
}
#define CP_COMMIT() asm volatile("cp.async.commit_group;" ::: "memory")
#define CP_WAIT0()  asm volatile("cp.async.wait_group 0;" ::: "memory")

#define LDSM_X4(r, addr)                                                      \
    asm volatile("ldmatrix.sync.aligned.m8n8.x4.shared.b16 {%0,%1,%2,%3}, [%4];" \
                 : "=r"((r)[0]), "=r"((r)[1]), "=r"((r)[2]), "=r"((r)[3])     \
                 : "r"(addr))

#define MMA16816(d, a, b0, b1)                                                \
    asm volatile("mma.sync.aligned.m16n8k16.row.col.f32.bf16.bf16.f32 "       \
                 "{%0,%1,%2,%3}, {%4,%5,%6,%7}, {%8,%9}, {%0,%1,%2,%3};"      \
                 : "+f"((d)[0]), "+f"((d)[1]), "+f"((d)[2]), "+f"((d)[3])     \
                 : "r"((a)[0]), "r"((a)[1]), "r"((a)[2]), "r"((a)[3]),        \
                   "r"(b0), "r"(b1))

// ---------------------------------------------------------------------------
// Prep: L2-normalize each 256-d row, emit split bf16 (hi, lo). 1 warp/row.
// ---------------------------------------------------------------------------
__global__ __launch_bounds__(256)
void prep_kernel(const float* __restrict__ imgs, const float* __restrict__ caps) {
    int gw   = blockIdx.x * 8 + (threadIdx.x >> 5);
    int lane = threadIdx.x & 31;
    const float* src;
    __nv_bfloat16 *dhi, *dlo;
    if (gw < MM) {
        src = imgs + (size_t)gw * DD;
        dhi = g_Ahi + (size_t)gw * DD;
        dlo = g_Alo + (size_t)gw * DD;
    } else {
        int g2 = gw - MM;
        if (g2 >= NN) return;
        src = caps + (size_t)g2 * DD;
        dhi = g_Bhi + (size_t)g2 * DD;
        dlo = g_Blo + (size_t)g2 * DD;
    }
    float4 x0 = ((const float4*)src)[lane];
    float4 x1 = ((const float4*)src)[lane + 32];
    float ss = x0.x*x0.x + x0.y*x0.y + x0.z*x0.z + x0.w*x0.w
             + x1.x*x1.x + x1.y*x1.y + x1.z*x1.z + x1.w*x1.w;
#pragma unroll
    for (int o = 16; o; o >>= 1) ss += __shfl_xor_sync(0xffffffffu, ss, o);
    float sc = 1.0f / fmaxf(sqrtf(ss), 1e-8f);
    float xs[8] = { x0.x*sc, x0.y*sc, x0.z*sc, x0.w*sc,
                    x1.x*sc, x1.y*sc, x1.z*sc, x1.w*sc };
#pragma unroll
    for (int h = 0; h < 2; h++) {
        int b = h * 128 + 4 * lane;
#pragma unroll
        for (int q = 0; q < 2; q++) {
            float a = xs[h*4 + q*2], c = xs[h*4 + q*2 + 1];
            __nv_bfloat16 ah = __float2bfloat16(a);
            __nv_bfloat16 ch = __float2bfloat16(c);
            __nv_bfloat16 al = __float2bfloat16(a - __bfloat162float(ah));
            __nv_bfloat16 cl = __float2bfloat16(c - __bfloat162float(ch));
            __nv_bfloat162 hv; hv.x = ah; hv.y = ch;
            __nv_bfloat162 lv; lv.x = al; lv.y = cl;
            ((__nv_bfloat162*)(dhi + b))[q] = hv;
            ((__nv_bfloat162*)(dlo + b))[q] = lv;
        }
    }
}

// ---------------------------------------------------------------------------
// Dense GEMM: C[4608 x 6400] = A * B^T, split-bf16 (hh + lh + hl), fp32 acc.
// (unchanged from R16 — protected win)
// ---------------------------------------------------------------------------
__global__ __launch_bounds__(256, 2)
void gemm_kernel() {
    extern __shared__ __align__(16) char smem[];
    const uint32_t sb = smem_u32(smem);
    const int tid = threadIdx.x, wid = tid >> 5, lane = tid & 31;
    const int wm = wid & 1, wn = wid >> 1;
    const int m0 = blockIdx.y * 128, n0 = blockIdx.x * 128;

    const uint32_t aoff = (uint32_t)((wm*64 + (lane & 15)) * RS + ((lane >> 4) & 1) * 16);
    const uint32_t boff = (uint32_t)((wn*32 + (lane & 7) + ((lane >> 4) * 8)) * RS
                                     + ((lane >> 3) & 1) * 16);
    const uint32_t a_hi = sb + T_AHI + aoff, a_lo = sb + T_ALO + aoff;
    const uint32_t b_hi = sb + T_BHI + boff, b_lo = sb + T_BLO + boff;

    float acc[4][4][4];
#pragma unroll
    for (int mb = 0; mb < 4; mb++)
#pragma unroll
        for (int j = 0; j < 4; j++)
#pragma unroll
            for (int e = 0; e < 4; e++) acc[mb][j][e] = 0.0f;

    for (int ch = 0; ch < 4; ch++) {
        const int kb = ch * 64;
        if (ch) __syncthreads();
        for (int t = tid; t < 1024; t += 256) {
            int mr = t >> 3, q = t & 7;
            uint32_t soff = (uint32_t)(mr * RS + q * 16);
            size_t ga = ((size_t)(m0 + mr)) * DD + kb + q * 8;
            size_t gb = ((size_t)(n0 + mr)) * DD + kb + q * 8;
            cp16(sb + T_AHI + soff, g_Ahi + ga);
            cp16(sb + T_ALO + soff, g_Alo + ga);
            cp16(sb + T_BHI + soff, g_Bhi + gb);
            cp16(sb + T_BLO + soff, g_Blo + gb);
        }
        CP_COMMIT(); CP_WAIT0();
        __syncthreads();

#pragma unroll
        for (int ks = 0; ks < 4; ks++) {
            const uint32_t ko = (uint32_t)(ks * 32);
            uint32_t ah[4][4], al[4][4], bb[2][4];
#pragma unroll
            for (int mb = 0; mb < 4; mb++) {
                LDSM_X4(ah[mb], a_hi + (uint32_t)(mb * 16 * RS) + ko);
                LDSM_X4(al[mb], a_lo + (uint32_t)(mb * 16 * RS) + ko);
            }
#pragma unroll
            for (int nb = 0; nb < 2; nb++)
                LDSM_X4(bb[nb], b_hi + (uint32_t)(nb * 16 * RS) + ko);
#pragma unroll
            for (int mb = 0; mb < 4; mb++)
#pragma unroll
                for (int j = 0; j < 4; j++)
                    MMA16816(acc[mb][j], ah[mb], bb[j >> 1][(j & 1) * 2], bb[j >> 1][(j & 1) * 2 + 1]);
#pragma unroll
            for (int mb = 0; mb < 4; mb++)
#pragma unroll
                for (int j = 0; j < 4; j++)
                    MMA16816(acc[mb][j], al[mb], bb[j >> 1][(j & 1) * 2], bb[j >> 1][(j & 1) * 2 + 1]);
#pragma unroll
            for (int nb = 0; nb < 2; nb++)
                LDSM_X4(bb[nb], b_lo + (uint32_t)(nb * 16 * RS) + ko);
#pragma unroll
            for (int mb = 0; mb < 4; mb++)
#pragma unroll
                for (int j = 0; j < 4; j++)
                    MMA16816(acc[mb][j], ah[mb], bb[j >> 1][(j & 1) * 2], bb[j >> 1][(j & 1) * 2 + 1]);
        }
    }

    {
        const int gr = lane >> 2, tg = lane & 3;
#pragma unroll
        for (int mb = 0; mb < 4; mb++) {
            int r0 = m0 + wm * 64 + mb * 16 + gr;
#pragma unroll
            for (int j = 0; j < 4; j++) {
                int c = n0 + wn * 32 + j * 8 + 2 * tg;
                float2 v0 = { acc[mb][j][0], acc[mb][j][1] };
                float2 v1 = { acc[mb][j][2], acc[mb][j][3] };
                *(float2*)&g_C[(size_t)r0 * NN + c]       = v0;
                *(float2*)&g_C[(size_t)(r0 + 8) * NN + c] = v1;
            }
        }
    }
}

// ---------------------------------------------------------------------------
// Sinkhorn body: all row loops break at nr (warp-uniform), WIDE=false removes
// the entire c1 (lanes 32..49) path. Dropped work is exact +0/x0 -> bit-identical.
// ---------------------------------------------------------------------------
template<bool WIDE>
__device__ __forceinline__ float sink_body(const float* __restrict__ Srow,
                                           int nr, int nw, int lane) {
    const float invr = 1.0f / (float)nr;
    const float invw = 1.0f / (float)nw;
    const int c0 = lane, c1 = lane + 32;
    float P0[RR];
    float P1[WIDE ? RR : 1];

    // init: P = exp(20(s-1)) masked; total sum (rows >= nr contribute exact 0)
    float loc = 0.0f;
#pragma unroll
    for (int r = 0; r < RR; r++) {
        if (r >= nr) break;
        float p0 = 0.0f, p1 = 0.0f;
        if (c0 < nw) p0 = __expf(20.0f * (Srow[(size_t)r * NN + c0] - 1.0f));
        P0[r] = p0;
        if (WIDE) {
            if (c1 < nw) p1 = __expf(20.0f * (Srow[(size_t)r * NN + c1] - 1.0f));
            P1[r] = p1;
        }
        loc += p0 + p1;
    }
#pragma unroll
    for (int o = 16; o; o >>= 1) loc += __shfl_xor_sync(0xffffffffu, loc, o);
    float sc = 1.0f / (loc + 1e-6f);
#pragma unroll
    for (int r = 0; r < RR; r++) {
        if (r >= nr) break;
        P0[r] *= sc;
        if (WIDE) P1[r] *= sc;
    }

#pragma unroll 1
    for (int it = 0; it < 3; it++) {
        // row rescale (uniform break keeps shfl converged)
#pragma unroll
        for (int r = 0; r < RR; r++) {
            if (r >= nr) break;
            float t = WIDE ? (P0[r] + P1[r]) : P0[r];
#pragma unroll
            for (int o = 16; o; o >>= 1) t += __shfl_xor_sync(0xffffffffu, t, o);
            float f = invr / (t + 1e-6f);
            P0[r] *= f;
            if (WIDE) P1[r] *= f;
        }
        // col rescale (lane-private columns)
        float v0s = 0.0f, v1s = 0.0f;
#pragma unroll
        for (int r = 0; r < RR; r++) {
            if (r >= nr) break;
            v0s += P0[r];
            if (WIDE) v1s += P1[r];
        }
        float f0 = ((c0 < nw) ? invw : 0.0f) / (v0s + 1e-6f);
        float f1 = WIDE ? ((c1 < nw) ? invw : 0.0f) / (v1s + 1e-6f) : 0.0f;
#pragma unroll
        for (int r = 0; r < RR; r++) {
            if (r >= nr) break;
            P0[r] *= f0;
            if (WIDE) P1[r] *= f1;
        }
    }

    // final: sum S*P
    float fin = 0.0f;
#pragma unroll
    for (int r = 0; r < RR; r++) {
        if (r >= nr) break;
        fin += Srow[(size_t)r * NN + c0] * P0[r];
        if (WIDE) fin += Srow[(size_t)r * NN + c1] * P1[r];
    }
#pragma unroll
    for (int o = 16; o; o >>= 1) fin += __shfl_xor_sync(0xffffffffu, fin, o);
    return fin;
}

__global__ __launch_bounds__(256)
void sink_kernel(const int* __restrict__ ilens, const int* __restrict__ clens,
                 float* __restrict__ out) {
    const int p = blockIdx.x * 8 + (threadIdx.x >> 5);
    const int lane = threadIdx.x & 31;
    const int i = p >> 7, j = p & 127;
    const int nr = ilens[i];
    const int nw = clens[j];
    const float* Srow = g_C + (size_t)(i * RR) * NN + j * WW;

    float fin = (nw > 32) ? sink_body<true >(Srow, nr, nw, lane)
                          : sink_body<false>(Srow, nr, nw, lane);
    if (lane == 0) out[i * NJ + j] = fin;
}

// ---------------------------------------------------------------------------
extern "C" void kernel_launch(void* const* d_in, const int* in_sizes, int n_in,
                              void* d_out, int out_size) {
    const float* imgs  = (const float*)d_in[0];
    const float* caps  = (const float*)d_in[1];
    const int*   ilens = (const int*)d_in[2];
    const int*   clens = (const int*)d_in[3];
    float* out = (float*)d_out;

    cudaFuncSetAttribute(gemm_kernel,
                         cudaFuncAttributeMaxDynamicSharedMemorySize, SMEM_TOTAL);

    const int total_rows = MM + NN;             // 11008 rows, 1 warp each
    int nblocks = (total_rows + 7) / 8;
    prep_kernel<<<nblocks, 256>>>(imgs, caps);

    dim3 ggrid(NN / 128, MM / 128);             // 50 x 36 = 1800 CTAs
    gemm_kernel<<<ggrid, 256, SMEM_TOTAL>>>();

    sink_kernel<<<(NI * NJ) / 8, 256>>>(ilens, clens, out);
}